// round 15
// baseline (speedup 1.0000x reference)
#include <cuda_runtime.h>
#include <cuda_fp16.h>
#include <cstdint>

// Problem constants (fixed by setup_inputs)
#define Rr      128
#define Nn      256
#define Dd      128
#define Hh      8
#define DHh     64
#define INNERi  512
#define MROWS   (Rr*Nn)      // 32768
#define PW      1536         // packed proj cols: 512 q | 512 k | 512 v
#define SWW     256          // seq-weight gemm cols: 128 ksw | 128 qsw
#define RSPLIT  8            // dots r-split planes (256 blocks)
#define LDH     72           // smem half pitch for 64-wide tiles (144B rows, 16B-aligned)
#define LDK     40           // hgemm k-slab pitch (80B rows, 16B-aligned)
#define LDP     136          // pairbias 128-wide LN row pitch

// ---------------- scratch (static device globals; no allocation) ----------------
__device__ __half g_proj [(size_t)MROWS*PW];     // 100 MB: q|k|v (half)
__device__ __half g_swp  [(size_t)MROWS*SWW];    // 16.8 MB: ksw|qsw (half)
__device__ __half g_xh   [(size_t)MROWS*Dd];     // x in half
__device__ __half g_WpT  [(size_t)PW*Dd];        // proj weights [n][k] half
__device__ __half g_WswT [(size_t)SWW*Dd];       // [swk_w|swq_w]^T [n][k] half
__device__ float  g_swb  [SWW];                  // [swk_b|swq_b]
__device__ __half g_woT  [Dd*INNERi];            // wo^T [n][k] half
__device__ float  g_w    [Nn*Hh*Rr];             // softmaxed row weights [n][h][r]
__device__ float  g_dots [(size_t)RSPLIT*Hh*Nn*Nn];
__device__ float  g_bias [Nn*Nn*Hh];             // pair bias -> heads [i][j][h]
__device__ __half g_attn [Hh*Nn*Nn];
__device__ __half g_ypre [(size_t)MROWS*INNERi]; // 32 MB

// ---------------- helpers --------------------------------------------------------
__device__ __forceinline__ void mma_f16(float* d, const uint32_t* a, const uint32_t* b) {
    asm volatile(
        "mma.sync.aligned.m16n8k16.row.col.f32.f16.f16.f32 "
        "{%0,%1,%2,%3}, {%4,%5,%6,%7}, {%8,%9}, {%0,%1,%2,%3};"
        : "+f"(d[0]), "+f"(d[1]), "+f"(d[2]), "+f"(d[3])
        : "r"(a[0]), "r"(a[1]), "r"(a[2]), "r"(a[3]), "r"(b[0]), "r"(b[1]));
}

__device__ __forceinline__ void ldsm_x4(uint32_t* r, uint32_t addr) {
    asm volatile("ldmatrix.sync.aligned.m8n8.x4.shared.b16 {%0,%1,%2,%3}, [%4];"
        : "=r"(r[0]), "=r"(r[1]), "=r"(r[2]), "=r"(r[3]) : "r"(addr));
}
__device__ __forceinline__ void ldsm_x2(uint32_t* r, uint32_t addr) {
    asm volatile("ldmatrix.sync.aligned.m8n8.x2.shared.b16 {%0,%1}, [%2];"
        : "=r"(r[0]), "=r"(r[1]) : "r"(addr));
}
__device__ __forceinline__ void ldsm_x2_trans(uint32_t* r, uint32_t addr) {
    asm volatile("ldmatrix.sync.aligned.m8n8.x2.trans.shared.b16 {%0,%1}, [%2];"
        : "=r"(r[0]), "=r"(r[1]) : "r"(addr));
}

__device__ __forceinline__ void cp16(void* smem, const void* gmem) {
    uint32_t s = (uint32_t)__cvta_generic_to_shared(smem);
    asm volatile("cp.async.cg.shared.global [%0], [%1], 16;\n" :: "r"(s), "l"(gmem));
}
#define CP_COMMIT() asm volatile("cp.async.commit_group;\n")
#define CP_WAIT1()  asm volatile("cp.async.wait_group 1;\n")

// ---------------- prep: x->half + pack all weights (one launch) ------------------
__global__ void prep_kernel(const float* __restrict__ x,
                            const float* __restrict__ wq,
                            const float* __restrict__ wkv,
                            const float* __restrict__ swkw,
                            const float* __restrict__ swkb,
                            const float* __restrict__ swqw,
                            const float* __restrict__ swqb,
                            const float* __restrict__ wo)
{
    int idx = blockIdx.x*blockDim.x + threadIdx.x;
    if (idx < MROWS*Dd/4) {
        int i4 = idx*4;
        float4 v = *(const float4*)&x[i4];
        __half2* p = (__half2*)&g_xh[i4];
        p[0] = __floats2half2_rn(v.x, v.y);
        p[1] = __floats2half2_rn(v.z, v.w);
    }
    if (idx < PW*Dd) {                              // [wq | wkv]^T
        int c = idx >> 7, k = idx & 127;
        float v = (c < 512) ? wq[k*512 + c] : wkv[k*1024 + (c-512)];
        g_WpT[idx] = __float2half(v);
    }
    if (idx < SWW*Dd) {                             // [swk_w | swq_w]^T
        int c = idx >> 7, k = idx & 127;
        float v = (c < 128) ? swkw[k*Dd + c] : swqw[k*Dd + (c-128)];
        g_WswT[idx] = __float2half(v);
    }
    if (idx < Dd*INNERi) {
        int n = idx >> 9, k = idx & 511;
        g_woT[idx] = __float2half(wo[k*Dd + n]);
    }
    if (idx < SWW)
        g_swb[idx] = (idx < 128) ? swkb[idx] : swqb[idx-128];
}

// ---------------- pipelined fp16 GEMM: C[M,N] = A[M,K] @ Bt[N,K]^T + bias --------
// nbase: column offset (proj split qk/v). EXITCOL: n0==EXITCOL only rows<256.
template<bool OUTH, int EXITCOL>
__global__ void __launch_bounds__(256)
hgemm_kernel(const __half* __restrict__ A, int lda,
             const __half* __restrict__ Bt, int ldb,
             const float* __restrict__ bias,
             void* __restrict__ Cv, int ldc, int K, int nbase)
{
    __shared__ __align__(16) __half As[2][128*LDK];
    __shared__ __align__(16) __half Bs[2][128*LDK];
    const int t = threadIdx.x;
    const int m0 = blockIdx.y*128, n0 = nbase + blockIdx.x*128;
    if (EXITCOL >= 0 && n0 == EXITCOL && m0 >= 256) return;
    const int wid = t >> 5, lane = t & 31;
    const int wm = (wid & 1)*64, wn = (wid >> 1)*32;
    const int g = lane >> 2, tig = lane & 3;
    const int lrow = t >> 2, lc8 = (t & 3)*8;
    const int aRow = ((lane>>3)&1)*8 + (lane&7);
    const int aCol = ((lane>>4)&1)*8;
    const int bRow = lane & 7;
    const int bCol = ((lane>>3)&1)*8;
    const uint32_t asB = (uint32_t)__cvta_generic_to_shared(&As[0][0]);
    const uint32_t bsB = (uint32_t)__cvta_generic_to_shared(&Bs[0][0]);
    float acc[4][4][4] = {};

    const int NT = K >> 5;
    #pragma unroll
    for (int u = 0; u < 2; u++) {
        int row = u*64 + lrow;
        cp16(&As[0][row*LDK + lc8], &A[(size_t)(m0+row)*lda + lc8]);
        cp16(&Bs[0][row*LDK + lc8], &Bt[(size_t)(n0+row)*ldb + lc8]);
    }
    CP_COMMIT();

    for (int kt = 0; kt < NT; kt++) {
        if (kt + 1 < NT) {
            int k0 = (kt+1) << 5, s = (kt+1) & 1;
            #pragma unroll
            for (int u = 0; u < 2; u++) {
                int row = u*64 + lrow;
                cp16(&As[s][row*LDK + lc8], &A[(size_t)(m0+row)*lda + k0 + lc8]);
                cp16(&Bs[s][row*LDK + lc8], &Bt[(size_t)(n0+row)*ldb + k0 + lc8]);
            }
        }
        CP_COMMIT();
        CP_WAIT1();
        __syncthreads();
        const uint32_t aBuf = asB + (uint32_t)((kt & 1)*128*LDK*2);
        const uint32_t bBuf = bsB + (uint32_t)((kt & 1)*128*LDK*2);
        #pragma unroll
        for (int ks = 0; ks < 2; ks++) {
            uint32_t af[4][4], bf[4][2];
            #pragma unroll
            for (int mf = 0; mf < 4; mf++)
                ldsm_x4(af[mf], aBuf + (uint32_t)(((wm + mf*16 + aRow)*LDK + ks*16 + aCol)*2));
            #pragma unroll
            for (int nf = 0; nf < 4; nf++)
                ldsm_x2(bf[nf], bBuf + (uint32_t)(((wn + nf*8 + bRow)*LDK + ks*16 + bCol)*2));
            #pragma unroll
            for (int mf = 0; mf < 4; mf++)
                #pragma unroll
                for (int nf = 0; nf < 4; nf++)
                    mma_f16(acc[mf][nf], af[mf], bf[nf]);
        }
        __syncthreads();
    }
    #pragma unroll
    for (int mf = 0; mf < 4; mf++) {
        int r0 = m0 + wm + mf*16 + g;
        #pragma unroll
        for (int nf = 0; nf < 4; nf++) {
            int c = n0 + wn + nf*8 + 2*tig;
            float b0 = 0.f, b1 = 0.f;
            if (bias) { b0 = bias[c]; b1 = bias[c+1]; }
            if (OUTH) {
                __half* C = (__half*)Cv;
                *(__half2*)&C[(size_t)r0*ldc + c] =
                    __floats2half2_rn(acc[mf][nf][0]+b0, acc[mf][nf][1]+b1);
                *(__half2*)&C[(size_t)(r0+8)*ldc + c] =
                    __floats2half2_rn(acc[mf][nf][2]+b0, acc[mf][nf][3]+b1);
            } else {
                float* C = (float*)Cv;
                *(float2*)&C[(size_t)r0*ldc + c] =
                    make_float2(acc[mf][nf][0]+b0, acc[mf][nf][1]+b1);
                *(float2*)&C[(size_t)(r0+8)*ldc + c] =
                    make_float2(acc[mf][nf][2]+b0, acc[mf][nf][3]+b1);
            }
        }
    }
}

// ---------------- seq-weight: block per n; thread r; reads g_swp -----------------
__global__ void __launch_bounds__(128)
seqw_kernel()
{
    const int n = blockIdx.x, r = threadIdx.x;
    __shared__ float qs[Dd];
    __shared__ float sm[Hh][132];
    __shared__ float smax[Hh], ssum[Hh];
    qs[r] = __half2float(g_swp[(size_t)n*SWW + 128 + r]);   // qsw (row 0 of MSA)
    __syncthreads();

    const __half* kp = g_swp + ((size_t)(r*Nn + n))*SWW;    // ksw row (contiguous)
    float sh[Hh] = {};
    #pragma unroll
    for (int q8 = 0; q8 < 16; q8++) {
        float4 raw = *(const float4*)(kp + q8*8);
        const __half2* h2 = (const __half2*)&raw;
        int h = q8 >> 1, d0 = (q8 & 1)*8;
        #pragma unroll
        for (int p = 0; p < 4; p++) {
            float2 f = __half22float2(h2[p]);
            sh[h] += qs[h*16 + d0 + 2*p]*f.x + qs[h*16 + d0 + 2*p + 1]*f.y;
        }
    }
    #pragma unroll
    for (int h = 0; h < Hh; h++) { sh[h] *= 0.25f; sm[h][r] = sh[h]; }
    __syncthreads();

    const int wid = r >> 5, lane = r & 31;
    #pragma unroll
    for (int hh = 0; hh < 2; hh++) {
        int h = wid*2 + hh;
        float m = fmaxf(fmaxf(sm[h][lane], sm[h][lane+32]),
                        fmaxf(sm[h][lane+64], sm[h][lane+96]));
        #pragma unroll
        for (int o = 16; o; o >>= 1) m = fmaxf(m, __shfl_xor_sync(0xffffffffu, m, o));
        if (lane == 0) smax[h] = m;
    }
    __syncthreads();
    float e[Hh];
    #pragma unroll
    for (int h = 0; h < Hh; h++) { e[h] = __expf(sh[h] - smax[h]); sm[h][r] = e[h]; }
    __syncthreads();
    #pragma unroll
    for (int hh = 0; hh < 2; hh++) {
        int h = wid*2 + hh;
        float s = sm[h][lane] + sm[h][lane+32] + sm[h][lane+64] + sm[h][lane+96];
        #pragma unroll
        for (int o = 16; o; o >>= 1) s += __shfl_xor_sync(0xffffffffu, s, o);
        if (lane == 0) ssum[h] = s;
    }
    __syncthreads();
    #pragma unroll
    for (int h = 0; h < Hh; h++)
        g_w[(n*Hh + h)*Rr + r] = e[h] / ssum[h];
}

// ---------------- pair bias: LN (1-pass) -> smem half (pitch LDP) -> MMA ---------
__global__ void __launch_bounds__(256)
pairbias_kernel(const float* __restrict__ pb, const float* __restrict__ gg,
                const float* __restrict__ bb, const float* __restrict__ wp)
{
    __shared__ __align__(16) __half lnS[128*LDP];
    __shared__ __align__(16) __half wpT[8*LDP];
    __shared__ float s_g[Dd], s_b[Dd];
    const int t = threadIdx.x, warp = t >> 5, lane = t & 31;
    if (t < Dd) { s_g[t] = gg[t]; s_b[t] = bb[t]; }
    for (int e = t; e < Dd*Hh; e += 256) {
        int c = e >> 3, h = e & 7;
        wpT[h*LDP + c] = __float2half(wp[e]);
    }
    __syncthreads();

    const int pbase = blockIdx.x*128;
    #pragma unroll 2
    for (int pp = 0; pp < 16; pp++) {
        int p = warp*16 + pp;
        const float* rowp = pb + (size_t)(pbase + p)*Dd;
        float v[4];
        #pragma unroll
        for (int u = 0; u < 4; u++) v[u] = rowp[lane + 32*u];
        float s = v[0]+v[1]+v[2]+v[3];
        float q = v[0]*v[0]+v[1]*v[1]+v[2]*v[2]+v[3]*v[3];
        #pragma unroll
        for (int o = 16; o; o >>= 1) {
            s += __shfl_xor_sync(0xffffffffu, s, o);
            q += __shfl_xor_sync(0xffffffffu, q, o);
        }
        const float mu = s*(1.f/128.f);
        const float rstd = rsqrtf(q*(1.f/128.f) - mu*mu + 1e-5f);
        #pragma unroll
        for (int u = 0; u < 4; u++) {
            int c = lane + 32*u;
            lnS[p*LDP + c] = __float2half((v[u]-mu)*rstd*s_g[c] + s_b[c]);
        }
    }
    __syncthreads();

    const int g = lane >> 2, tig = lane & 3;
    float acc[4] = {};
    #pragma unroll
    for (int ks = 0; ks < 8; ks++) {
        uint32_t a[4], b[2];
        const __half* ap = &lnS[(warp*16 + g)*LDP + ks*16 + 2*tig];
        a[0] = *(const uint32_t*)ap;
        a[1] = *(const uint32_t*)(ap + 8*LDP);
        a[2] = *(const uint32_t*)(ap + 8);
        a[3] = *(const uint32_t*)(ap + 8*LDP + 8);
        const __half* bp = &wpT[g*LDP + ks*16 + 2*tig];
        b[0] = *(const uint32_t*)bp;
        b[1] = *(const uint32_t*)(bp + 8);
        mma_f16(acc, a, b);
    }
    int p0 = pbase + warp*16 + g;
    *(float2*)&g_bias[(size_t)p0*8 + 2*tig]     = make_float2(acc[0], acc[1]);
    *(float2*)&g_bias[(size_t)(p0+8)*8 + 2*tig] = make_float2(acc[2], acc[3]);
}

// ---------------- tied dots (fp16 MMA, reg-prefetch + ldmatrix) ------------------
__global__ void __launch_bounds__(256)
dots_f16_kernel()
{
    __shared__ __align__(16) __half Qs[128*LDH];
    __shared__ __align__(16) __half Ks[128*LDH];
    const int t = threadIdx.x;
    const int j0 = blockIdx.x*128, i0 = blockIdx.y*128;
    const int h = blockIdx.z & 7, rc = blockIdx.z >> 3;
    const int wid = t >> 5, lane = t & 31;
    const int wm = (wid & 1)*64, wn = (wid >> 1)*32;
    const int g = lane >> 2, tig = lane & 3;
    const int rowb = t >> 3, c8 = (t & 7)*8;
    const int aRow = ((lane>>3)&1)*8 + (lane&7);
    const int aCol = ((lane>>4)&1)*8;
    const int bRow = lane & 7;
    const int bCol = ((lane>>3)&1)*8;
    const uint32_t qsB = (uint32_t)__cvta_generic_to_shared(&Qs[0]);
    const uint32_t ksB = (uint32_t)__cvta_generic_to_shared(&Ks[0]);
    float acc[4][4][4] = {};
    float4 q4[4], k4[4]; float sc[4];

    const int rbeg = rc*(Rr/RSPLIT), rend = rbeg + Rr/RSPLIT;

    #pragma unroll
    for (int u = 0; u < 4; u++) {
        int row = u*32 + rowb;
        q4[u] = *(const float4*)(g_proj + ((size_t)(rbeg*Nn + i0+row))*PW + h*64 + c8);
        k4[u] = *(const float4*)(g_proj + ((size_t)(rbeg*Nn + j0+row))*PW + 512 + h*64 + c8);
        sc[u] = g_w[((i0+row)*Hh + h)*Rr + rbeg];
    }

    for (int r = rbeg; r < rend; ++r) {
        #pragma unroll
        for (int u = 0; u < 4; u++) {
            int row = u*32 + rowb;
            float4 a = q4[u];
            __half2 sc2 = __float2half2_rn(sc[u]);
            __half2* ah = (__half2*)&a;
            ah[0] = __hmul2(ah[0], sc2); ah[1] = __hmul2(ah[1], sc2);
            ah[2] = __hmul2(ah[2], sc2); ah[3] = __hmul2(ah[3], sc2);
            *(float4*)&Qs[row*LDH + c8] = a;
            *(float4*)&Ks[row*LDH + c8] = k4[u];
        }
        __syncthreads();
        if (r + 1 < rend) {
            #pragma unroll
            for (int u = 0; u < 4; u++) {
                int row = u*32 + rowb;
                q4[u] = *(const float4*)(g_proj + ((size_t)((r+1)*Nn + i0+row))*PW + h*64 + c8);
                k4[u] = *(const float4*)(g_proj + ((size_t)((r+1)*Nn + j0+row))*PW + 512 + h*64 + c8);
                sc[u] = g_w[((i0+row)*Hh + h)*Rr + r+1];
            }
        }
        #pragma unroll
        for (int ks = 0; ks < 4; ks++) {
            uint32_t af[4][4], bf[4][2];
            #pragma unroll
            for (int mf = 0; mf < 4; mf++)
                ldsm_x4(af[mf], qsB + (uint32_t)(((wm + mf*16 + aRow)*LDH + ks*16 + aCol)*2));
            #pragma unroll
            for (int nf = 0; nf < 4; nf++)
                ldsm_x2(bf[nf], ksB + (uint32_t)(((wn + nf*8 + bRow)*LDH + ks*16 + bCol)*2));
            #pragma unroll
            for (int mf = 0; mf < 4; mf++)
                #pragma unroll
                for (int nf = 0; nf < 4; nf++)
                    mma_f16(acc[mf][nf], af[mf], bf[nf]);
        }
        __syncthreads();
    }
    float* plane = g_dots + ((size_t)(rc*Hh + h))*Nn*Nn;
    #pragma unroll
    for (int mf = 0; mf < 4; mf++) {
        int i = i0 + wm + mf*16 + g;
        #pragma unroll
        for (int nf = 0; nf < 4; nf++) {
            int j = j0 + wn + nf*8 + 2*tig;
            *(float2*)&plane[(size_t)i*Nn + j] =
                make_float2(acc[mf][nf][0]*0.125f, acc[mf][nf][1]*0.125f);
            *(float2*)&plane[(size_t)(i+8)*Nn + j] =
                make_float2(acc[mf][nf][2]*0.125f, acc[mf][nf][3]*0.125f);
        }
    }
}

// ---------------- attention softmax over j (sums RSPLIT planes), half out --------
__global__ void __launch_bounds__(256)
softmax_kernel()
{
    const int row = blockIdx.x;            // h*256 + i
    const int h = row >> 8, i = row & 255, j = threadIdx.x;
    float v = g_bias[((size_t)i*Nn + j)*Hh + h];
    #pragma unroll
    for (int p = 0; p < RSPLIT; p++)
        v += g_dots[(((size_t)(p*Hh + h))*Nn + i)*Nn + j];
    __shared__ float red[8];
    const int lane = j & 31, wid = j >> 5;
    float m = v;
    #pragma unroll
    for (int o = 16; o; o >>= 1) m = fmaxf(m, __shfl_xor_sync(0xffffffffu, m, o));
    if (lane == 0) red[wid] = m;
    __syncthreads();
    float bm = red[0];
    #pragma unroll
    for (int k = 1; k < 8; k++) bm = fmaxf(bm, red[k]);
    __syncthreads();
    float e = __expf(v - bm);
    float s = e;
    #pragma unroll
    for (int o = 16; o; o >>= 1) s += __shfl_xor_sync(0xffffffffu, s, o);
    if (lane == 0) red[wid] = s;
    __syncthreads();
    float su = red[0];
    #pragma unroll
    for (int k = 1; k < 8; k++) su += red[k];
    g_attn[(size_t)row*Nn + j] = __float2half(e/su);
}

// ---------------- attn@V v2: one block per (h,r) covers ALL 256 i-rows -----------
__global__ void __launch_bounds__(256)
attnv_f16_kernel()
{
    __shared__ __align__(16) __half As[256*LDH];    // attn [i][j-slab]
    __shared__ __align__(16) __half Vs[64*LDH];     // v [j][d] (plain rows)
    const int t = threadIdx.x;
    const int h = blockIdx.x, r = blockIdx.y;
    const int wid = t >> 5, lane = t & 31;
    const int wm = (wid & 3)*64, wn = (wid >> 2)*32;
    const int g = lane >> 2, tig = lane & 3;
    const int rowb = t >> 3, c8 = (t & 7)*8;
    const int aRow = ((lane>>3)&1)*8 + (lane&7);
    const int aCol = ((lane>>4)&1)*8;
    const int tRow = (lane & 7) + ((lane>>3)&1)*8;
    const uint32_t asB = (uint32_t)__cvta_generic_to_shared(&As[0]);
    const uint32_t vsB = (uint32_t)__cvta_generic_to_shared(&Vs[0]);
    float acc[4][4][4] = {};
    float4 a4[8], b4[2];

    #pragma unroll
    for (int u = 0; u < 8; u++)
        a4[u] = *(const float4*)(g_attn + ((size_t)(h*Nn + u*32+rowb))*Nn + c8);
    #pragma unroll
    for (int u = 0; u < 2; u++)
        b4[u] = *(const float4*)(g_proj + ((size_t)(r*Nn + u*32+rowb))*PW + 1024 + h*64 + c8);

    for (int kt = 0; kt < 4; kt++) {
        #pragma unroll
        for (int u = 0; u < 8; u++)
            *(float4*)&As[(u*32+rowb)*LDH + c8] = a4[u];
        #pragma unroll
        for (int u = 0; u < 2; u++)
            *(float4*)&Vs[(u*32+rowb)*LDH + c8] = b4[u];
        __syncthreads();
        if (kt < 3) {
            int k0 = (kt+1)*64;
            #pragma unroll
            for (int u = 0; u < 8; u++)
                a4[u] = *(const float4*)(g_attn + ((size_t)(h*Nn + u*32+rowb))*Nn + k0 + c8);
            #pragma unroll
            for (int u = 0; u < 2; u++)
                b4[u] = *(const float4*)(g_proj + ((size_t)(r*Nn + k0 + u*32+rowb))*PW + 1024 + h*64 + c8);
        }
        #pragma unroll
        for (int ks = 0; ks < 4; ks++) {
            uint32_t af[4][4], bf[4][2];
            #pragma unroll
            for (int mf = 0; mf < 4; mf++)
                ldsm_x4(af[mf], asB + (uint32_t)(((wm + mf*16 + aRow)*LDH + ks*16 + aCol)*2));
            #pragma unroll
            for (int nf = 0; nf < 4; nf++)
                ldsm_x2_trans(bf[nf], vsB + (uint32_t)(((ks*16 + tRow)*LDH + wn + nf*8)*2));
            #pragma unroll
            for (int mf = 0; mf < 4; mf++)
                #pragma unroll
                for (int nf = 0; nf < 4; nf++)
                    mma_f16(acc[mf][nf], af[mf], bf[nf]);
        }
        __syncthreads();
    }
    #pragma unroll
    for (int mf = 0; mf < 4; mf++) {
        int i = wm + mf*16 + g;
        #pragma unroll
        for (int nf = 0; nf < 4; nf++) {
            int c = h*64 + wn + nf*8 + 2*tig;
            *(__half2*)&g_ypre[((size_t)(r*Nn) + i)*INNERi + c] =
                __floats2half2_rn(acc[mf][nf][0], acc[mf][nf][1]);
            *(__half2*)&g_ypre[((size_t)(r*Nn) + i + 8)*INNERi + c] =
                __floats2half2_rn(acc[mf][nf][2], acc[mf][nf][3]);
        }
    }
}

// =================================================================================
extern "C" void kernel_launch(void* const* d_in, const int* in_sizes, int n_in,
                              void* d_out, int out_size)
{
    const float* x    = (const float*)d_in[0];
    const float* pair = (const float*)d_in[1];
    const float* wq   = (const float*)d_in[2];
    const float* wkv  = (const float*)d_in[3];
    const float* wo   = (const float*)d_in[4];
    const float* bo   = (const float*)d_in[5];
    const float* png  = (const float*)d_in[6];
    const float* pnb  = (const float*)d_in[7];
    const float* wp   = (const float*)d_in[8];
    const float* swqw = (const float*)d_in[9];
    const float* swqb = (const float*)d_in[10];
    const float* swkw = (const float*)d_in[11];
    const float* swkb = (const float*)d_in[12];
    float* out = (float*)d_out;

    __half *projh, *swph, *xh, *WpT, *WswT, *woT, *ypre;
    float *swb;
    cudaGetSymbolAddress((void**)&projh, g_proj);
    cudaGetSymbolAddress((void**)&swph,  g_swp);
    cudaGetSymbolAddress((void**)&xh,    g_xh);
    cudaGetSymbolAddress((void**)&WpT,   g_WpT);
    cudaGetSymbolAddress((void**)&WswT,  g_WswT);
    cudaGetSymbolAddress((void**)&woT,   g_woT);
    cudaGetSymbolAddress((void**)&ypre,  g_ypre);
    cudaGetSymbolAddress((void**)&swb,   g_swb);

    // side stream + events, created once on first (uncaptured) call
    static cudaStream_t s2 = nullptr;
    static cudaEvent_t evFork = nullptr, evPrep = nullptr, evSide = nullptr, evV = nullptr;
    if (s2 == nullptr) {
        cudaStreamCreateWithFlags(&s2, cudaStreamNonBlocking);
        cudaEventCreateWithFlags(&evFork, cudaEventDisableTiming);
        cudaEventCreateWithFlags(&evPrep, cudaEventDisableTiming);
        cudaEventCreateWithFlags(&evSide, cudaEventDisableTiming);
        cudaEventCreateWithFlags(&evV,    cudaEventDisableTiming);
    }

    // fork: pairbias first on s2 (depends only on kernel inputs)
    cudaEventRecord(evFork, 0);
    cudaStreamWaitEvent(s2, evFork, 0);
    pairbias_kernel<<<Nn*Nn/128, 256, 0, s2>>>(pair, png, pnb, wp);

    // main: prep (x->half + weight packs)
    prep_kernel<<<(MROWS*Dd/4 + 255)/256, 256>>>(x, wq, wkv, swkw, swkb, swqw, swqb, wo);
    cudaEventRecord(evPrep, 0);

    // s2 (after prep): sw-gemm + seqw, then proj_v (cols 1024..1535)
    cudaStreamWaitEvent(s2, evPrep, 0);
    hgemm_kernel<true, 128><<<dim3(SWW/128, MROWS/128), 256, 0, s2>>>(
        xh, Dd, WswT, Dd, swb, swph, SWW, Dd, 0);
    seqw_kernel<<<Nn, 128, 0, s2>>>();
    cudaEventRecord(evSide, s2);
    hgemm_kernel<true, -1><<<dim3(4, MROWS/128), 256, 0, s2>>>(
        xh, Dd, WpT, Dd, nullptr, projh, PW, Dd, 1024);
    cudaEventRecord(evV, s2);

    // main: proj q|k (cols 0..1023)
    hgemm_kernel<true, -1><<<dim3(8, MROWS/128), 256>>>(
        xh, Dd, WpT, Dd, nullptr, projh, PW, Dd, 0);

    // join: dots needs g_w (and transitively pairbias, ordered before evSide on s2)
    cudaStreamWaitEvent(0, evSide, 0);
    dots_f16_kernel<<<dim3(Nn/128, Nn/128, RSPLIT*Hh), 256>>>();
    softmax_kernel<<<Hh*Nn, 256>>>();
    // join: attnv needs v from proj_v
    cudaStreamWaitEvent(0, evV, 0);
    attnv_f16_kernel<<<dim3(Hh, Rr), 256>>>();
    hgemm_kernel<false, -1><<<dim3(Dd/128, MROWS/128), 256>>>(
        ypre, INNERi, woT, INNERi, bo, out, Dd, INNERi, 0);
}

// round 17
// speedup vs baseline: 1.0187x; 1.0187x over previous
#include <cuda_runtime.h>
#include <cuda_fp16.h>
#include <cstdint>

// Problem constants (fixed by setup_inputs)
#define Rr      128
#define Nn      256
#define Dd      128
#define Hh      8
#define DHh     64
#define INNERi  512
#define MROWS   (Rr*Nn)      // 32768
#define PW      1536         // packed proj cols: 512 q | 512 k | 512 v
#define SWW     256          // seq-weight gemm cols: 128 ksw | 128 qsw
#define RSPLIT  8            // dots r-split planes (256 blocks)
#define LDH     72           // smem half pitch for 64-wide tiles (144B rows, 16B-aligned)
#define LDK     40           // hgemm k-slab pitch (80B rows, 16B-aligned)
#define LDP     136          // pairbias 128-wide LN row pitch
#define AVSMEM  (2*(256*LDH + 64*LDH)*2)   // attnv dynamic smem: 92160 B

// ---------------- scratch (static device globals; no allocation) ----------------
__device__ __half g_proj [(size_t)MROWS*PW];     // 100 MB: q|k|v (half)
__device__ __half g_swp  [(size_t)MROWS*SWW];    // 16.8 MB: ksw|qsw (half)
__device__ __half g_xh   [(size_t)MROWS*Dd];     // x in half
__device__ __half g_WpT  [(size_t)PW*Dd];        // proj weights [n][k] half
__device__ __half g_WswT [(size_t)SWW*Dd];       // [swk_w|swq_w]^T [n][k] half
__device__ float  g_swb  [SWW];                  // [swk_b|swq_b]
__device__ __half g_woT  [Dd*INNERi];            // wo^T [n][k] half
__device__ float  g_w    [Nn*Hh*Rr];             // softmaxed row weights [n][h][r]
__device__ float  g_dots [(size_t)RSPLIT*Hh*Nn*Nn];
__device__ float  g_bias [(size_t)Hh*Nn*Nn];     // pair bias, TRANSPOSED: [h][i][j]
__device__ __half g_attn [Hh*Nn*Nn];
__device__ __half g_ypre [(size_t)MROWS*INNERi]; // 32 MB

// ---------------- helpers --------------------------------------------------------
__device__ __forceinline__ void mma_f16(float* d, const uint32_t* a, const uint32_t* b) {
    asm volatile(
        "mma.sync.aligned.m16n8k16.row.col.f32.f16.f16.f32 "
        "{%0,%1,%2,%3}, {%4,%5,%6,%7}, {%8,%9}, {%0,%1,%2,%3};"
        : "+f"(d[0]), "+f"(d[1]), "+f"(d[2]), "+f"(d[3])
        : "r"(a[0]), "r"(a[1]), "r"(a[2]), "r"(a[3]), "r"(b[0]), "r"(b[1]));
}

__device__ __forceinline__ void ldsm_x4(uint32_t* r, uint32_t addr) {
    asm volatile("ldmatrix.sync.aligned.m8n8.x4.shared.b16 {%0,%1,%2,%3}, [%4];"
        : "=r"(r[0]), "=r"(r[1]), "=r"(r[2]), "=r"(r[3]) : "r"(addr));
}
__device__ __forceinline__ void ldsm_x2(uint32_t* r, uint32_t addr) {
    asm volatile("ldmatrix.sync.aligned.m8n8.x2.shared.b16 {%0,%1}, [%2];"
        : "=r"(r[0]), "=r"(r[1]) : "r"(addr));
}
__device__ __forceinline__ void ldsm_x2_trans(uint32_t* r, uint32_t addr) {
    asm volatile("ldmatrix.sync.aligned.m8n8.x2.trans.shared.b16 {%0,%1}, [%2];"
        : "=r"(r[0]), "=r"(r[1]) : "r"(addr));
}

__device__ __forceinline__ void cp16(void* smem, const void* gmem) {
    uint32_t s = (uint32_t)__cvta_generic_to_shared(smem);
    asm volatile("cp.async.cg.shared.global [%0], [%1], 16;\n" :: "r"(s), "l"(gmem));
}
#define CP_COMMIT() asm volatile("cp.async.commit_group;\n")
#define CP_WAIT1()  asm volatile("cp.async.wait_group 1;\n")

// ---------------- prep: x->half + pack all weights (one launch) ------------------
__global__ void prep_kernel(const float* __restrict__ x,
                            const float* __restrict__ wq,
                            const float* __restrict__ wkv,
                            const float* __restrict__ swkw,
                            const float* __restrict__ swkb,
                            const float* __restrict__ swqw,
                            const float* __restrict__ swqb,
                            const float* __restrict__ wo)
{
    int idx = blockIdx.x*blockDim.x + threadIdx.x;
    if (idx < MROWS*Dd/4) {
        int i4 = idx*4;
        float4 v = *(const float4*)&x[i4];
        __half2* p = (__half2*)&g_xh[i4];
        p[0] = __floats2half2_rn(v.x, v.y);
        p[1] = __floats2half2_rn(v.z, v.w);
    }
    if (idx < PW*Dd) {                              // [wq | wkv]^T
        int c = idx >> 7, k = idx & 127;
        float v = (c < 512) ? wq[k*512 + c] : wkv[k*1024 + (c-512)];
        g_WpT[idx] = __float2half(v);
    }
    if (idx < SWW*Dd) {                             // [swk_w | swq_w]^T
        int c = idx >> 7, k = idx & 127;
        float v = (c < 128) ? swkw[k*Dd + c] : swqw[k*Dd + (c-128)];
        g_WswT[idx] = __float2half(v);
    }
    if (idx < Dd*INNERi) {
        int n = idx >> 9, k = idx & 511;
        g_woT[idx] = __float2half(wo[k*Dd + n]);
    }
    if (idx < SWW)
        g_swb[idx] = (idx < 128) ? swkb[idx] : swqb[idx-128];
}

// ---------------- pipelined fp16 GEMM: C[M,N] = A[M,K] @ Bt[N,K]^T + bias --------
// EXITCOL: n0==EXITCOL tiles only needed for rows < 256 (qsw early exit)
template<bool OUTH, int EXITCOL>
__global__ void __launch_bounds__(256)
hgemm_kernel(const __half* __restrict__ A, int lda,
             const __half* __restrict__ Bt, int ldb,
             const float* __restrict__ bias,
             void* __restrict__ Cv, int ldc, int K)
{
    __shared__ __align__(16) __half As[2][128*LDK];
    __shared__ __align__(16) __half Bs[2][128*LDK];
    const int t = threadIdx.x;
    const int m0 = blockIdx.y*128, n0 = blockIdx.x*128;
    if (EXITCOL >= 0 && n0 == EXITCOL && m0 >= 256) return;
    const int wid = t >> 5, lane = t & 31;
    const int wm = (wid & 1)*64, wn = (wid >> 1)*32;
    const int g = lane >> 2, tig = lane & 3;
    const int lrow = t >> 2, lc8 = (t & 3)*8;
    const int aRow = ((lane>>3)&1)*8 + (lane&7);
    const int aCol = ((lane>>4)&1)*8;
    const int bRow = lane & 7;
    const int bCol = ((lane>>3)&1)*8;
    const uint32_t asB = (uint32_t)__cvta_generic_to_shared(&As[0][0]);
    const uint32_t bsB = (uint32_t)__cvta_generic_to_shared(&Bs[0][0]);
    float acc[4][4][4] = {};

    const int NT = K >> 5;
    #pragma unroll
    for (int u = 0; u < 2; u++) {
        int row = u*64 + lrow;
        cp16(&As[0][row*LDK + lc8], &A[(size_t)(m0+row)*lda + lc8]);
        cp16(&Bs[0][row*LDK + lc8], &Bt[(size_t)(n0+row)*ldb + lc8]);
    }
    CP_COMMIT();

    for (int kt = 0; kt < NT; kt++) {
        if (kt + 1 < NT) {
            int k0 = (kt+1) << 5, s = (kt+1) & 1;
            #pragma unroll
            for (int u = 0; u < 2; u++) {
                int row = u*64 + lrow;
                cp16(&As[s][row*LDK + lc8], &A[(size_t)(m0+row)*lda + k0 + lc8]);
                cp16(&Bs[s][row*LDK + lc8], &Bt[(size_t)(n0+row)*ldb + k0 + lc8]);
            }
        }
        CP_COMMIT();
        CP_WAIT1();
        __syncthreads();
        const uint32_t aBuf = asB + (uint32_t)((kt & 1)*128*LDK*2);
        const uint32_t bBuf = bsB + (uint32_t)((kt & 1)*128*LDK*2);
        #pragma unroll
        for (int ks = 0; ks < 2; ks++) {
            uint32_t af[4][4], bf[4][2];
            #pragma unroll
            for (int mf = 0; mf < 4; mf++)
                ldsm_x4(af[mf], aBuf + (uint32_t)(((wm + mf*16 + aRow)*LDK + ks*16 + aCol)*2));
            #pragma unroll
            for (int nf = 0; nf < 4; nf++)
                ldsm_x2(bf[nf], bBuf + (uint32_t)(((wn + nf*8 + bRow)*LDK + ks*16 + bCol)*2));
            #pragma unroll
            for (int mf = 0; mf < 4; mf++)
                #pragma unroll
                for (int nf = 0; nf < 4; nf++)
                    mma_f16(acc[mf][nf], af[mf], bf[nf]);
        }
        __syncthreads();
    }
    #pragma unroll
    for (int mf = 0; mf < 4; mf++) {
        int r0 = m0 + wm + mf*16 + g;
        #pragma unroll
        for (int nf = 0; nf < 4; nf++) {
            int c = n0 + wn + nf*8 + 2*tig;
            float b0 = 0.f, b1 = 0.f;
            if (bias) { b0 = bias[c]; b1 = bias[c+1]; }
            if (OUTH) {
                __half* C = (__half*)Cv;
                *(__half2*)&C[(size_t)r0*ldc + c] =
                    __floats2half2_rn(acc[mf][nf][0]+b0, acc[mf][nf][1]+b1);
                *(__half2*)&C[(size_t)(r0+8)*ldc + c] =
                    __floats2half2_rn(acc[mf][nf][2]+b0, acc[mf][nf][3]+b1);
            } else {
                float* C = (float*)Cv;
                *(float2*)&C[(size_t)r0*ldc + c] =
                    make_float2(acc[mf][nf][0]+b0, acc[mf][nf][1]+b1);
                *(float2*)&C[(size_t)(r0+8)*ldc + c] =
                    make_float2(acc[mf][nf][2]+b0, acc[mf][nf][3]+b1);
            }
        }
    }
}

// ---------------- seq-weight: block per n; thread r; reads g_swp -----------------
__global__ void __launch_bounds__(128)
seqw_kernel()
{
    const int n = blockIdx.x, r = threadIdx.x;
    __shared__ float qs[Dd];
    __shared__ float sm[Hh][132];
    __shared__ float smax[Hh], ssum[Hh];
    qs[r] = __half2float(g_swp[(size_t)n*SWW + 128 + r]);   // qsw (row 0 of MSA)
    __syncthreads();

    const __half* kp = g_swp + ((size_t)(r*Nn + n))*SWW;    // ksw row (contiguous)
    float sh[Hh] = {};
    #pragma unroll
    for (int q8 = 0; q8 < 16; q8++) {
        float4 raw = *(const float4*)(kp + q8*8);
        const __half2* h2 = (const __half2*)&raw;
        int h = q8 >> 1, d0 = (q8 & 1)*8;
        #pragma unroll
        for (int p = 0; p < 4; p++) {
            float2 f = __half22float2(h2[p]);
            sh[h] += qs[h*16 + d0 + 2*p]*f.x + qs[h*16 + d0 + 2*p + 1]*f.y;
        }
    }
    #pragma unroll
    for (int h = 0; h < Hh; h++) { sh[h] *= 0.25f; sm[h][r] = sh[h]; }
    __syncthreads();

    const int wid = r >> 5, lane = r & 31;
    #pragma unroll
    for (int hh = 0; hh < 2; hh++) {
        int h = wid*2 + hh;
        float m = fmaxf(fmaxf(sm[h][lane], sm[h][lane+32]),
                        fmaxf(sm[h][lane+64], sm[h][lane+96]));
        #pragma unroll
        for (int o = 16; o; o >>= 1) m = fmaxf(m, __shfl_xor_sync(0xffffffffu, m, o));
        if (lane == 0) smax[h] = m;
    }
    __syncthreads();
    float e[Hh];
    #pragma unroll
    for (int h = 0; h < Hh; h++) { e[h] = __expf(sh[h] - smax[h]); sm[h][r] = e[h]; }
    __syncthreads();
    #pragma unroll
    for (int hh = 0; hh < 2; hh++) {
        int h = wid*2 + hh;
        float s = sm[h][lane] + sm[h][lane+32] + sm[h][lane+64] + sm[h][lane+96];
        #pragma unroll
        for (int o = 16; o; o >>= 1) s += __shfl_xor_sync(0xffffffffu, s, o);
        if (lane == 0) ssum[h] = s;
    }
    __syncthreads();
    #pragma unroll
    for (int h = 0; h < Hh; h++)
        g_w[(n*Hh + h)*Rr + r] = e[h] / ssum[h];
}

// ---------------- pair bias: LN -> smem half -> MMA; OUTPUT TRANSPOSED [h][i][j] --
__global__ void __launch_bounds__(256)
pairbias_kernel(const float* __restrict__ pb, const float* __restrict__ gg,
                const float* __restrict__ bb, const float* __restrict__ wp)
{
    __shared__ __align__(16) __half lnS[128*LDP];
    __shared__ __align__(16) __half wpT[8*LDP];
    __shared__ float s_g[Dd], s_b[Dd];
    const int t = threadIdx.x, warp = t >> 5, lane = t & 31;
    if (t < Dd) { s_g[t] = gg[t]; s_b[t] = bb[t]; }
    for (int e = t; e < Dd*Hh; e += 256) {
        int c = e >> 3, h = e & 7;
        wpT[h*LDP + c] = __float2half(wp[e]);
    }
    __syncthreads();

    const int pbase = blockIdx.x*128;
    #pragma unroll 2
    for (int pp = 0; pp < 16; pp++) {
        int p = warp*16 + pp;
        const float* rowp = pb + (size_t)(pbase + p)*Dd;
        float v[4];
        #pragma unroll
        for (int u = 0; u < 4; u++) v[u] = rowp[lane + 32*u];
        float s = v[0]+v[1]+v[2]+v[3];
        float q = v[0]*v[0]+v[1]*v[1]+v[2]*v[2]+v[3]*v[3];
        #pragma unroll
        for (int o = 16; o; o >>= 1) {
            s += __shfl_xor_sync(0xffffffffu, s, o);
            q += __shfl_xor_sync(0xffffffffu, q, o);
        }
        const float mu = s*(1.f/128.f);
        const float rstd = rsqrtf(q*(1.f/128.f) - mu*mu + 1e-5f);
        #pragma unroll
        for (int u = 0; u < 4; u++) {
            int c = lane + 32*u;
            lnS[p*LDP + c] = __float2half((v[u]-mu)*rstd*s_g[c] + s_b[c]);
        }
    }
    __syncthreads();

    const int g = lane >> 2, tig = lane & 3;
    float acc[4] = {};
    #pragma unroll
    for (int ks = 0; ks < 8; ks++) {
        uint32_t a[4], b[2];
        const __half* ap = &lnS[(warp*16 + g)*LDP + ks*16 + 2*tig];
        a[0] = *(const uint32_t*)ap;
        a[1] = *(const uint32_t*)(ap + 8*LDP);
        a[2] = *(const uint32_t*)(ap + 8);
        a[3] = *(const uint32_t*)(ap + 8*LDP + 8);
        const __half* bp = &wpT[g*LDP + ks*16 + 2*tig];
        b[0] = *(const uint32_t*)bp;
        b[1] = *(const uint32_t*)(bp + 8);
        mma_f16(acc, a, b);
    }
    // acc = {(p0,h0),(p0,h1),(p0+8,h0),(p0+8,h1)} with h0=2*tig, h1=2*tig+1
    int p0 = pbase + warp*16 + g;
    g_bias[(size_t)(2*tig  )*Nn*Nn + p0    ] = acc[0];
    g_bias[(size_t)(2*tig+1)*Nn*Nn + p0    ] = acc[1];
    g_bias[(size_t)(2*tig  )*Nn*Nn + p0 + 8] = acc[2];
    g_bias[(size_t)(2*tig+1)*Nn*Nn + p0 + 8] = acc[3];
}

// ---------------- tied dots (fp16 MMA, reg-prefetch + ldmatrix) ------------------
__global__ void __launch_bounds__(256)
dots_f16_kernel()
{
    __shared__ __align__(16) __half Qs[128*LDH];
    __shared__ __align__(16) __half Ks[128*LDH];
    const int t = threadIdx.x;
    const int j0 = blockIdx.x*128, i0 = blockIdx.y*128;
    const int h = blockIdx.z & 7, rc = blockIdx.z >> 3;
    const int wid = t >> 5, lane = t & 31;
    const int wm = (wid & 1)*64, wn = (wid >> 1)*32;
    const int g = lane >> 2, tig = lane & 3;
    const int rowb = t >> 3, c8 = (t & 7)*8;
    const int aRow = ((lane>>3)&1)*8 + (lane&7);
    const int aCol = ((lane>>4)&1)*8;
    const int bRow = lane & 7;
    const int bCol = ((lane>>3)&1)*8;
    const uint32_t qsB = (uint32_t)__cvta_generic_to_shared(&Qs[0]);
    const uint32_t ksB = (uint32_t)__cvta_generic_to_shared(&Ks[0]);
    float acc[4][4][4] = {};
    float4 q4[4], k4[4]; float sc[4];

    const int rbeg = rc*(Rr/RSPLIT), rend = rbeg + Rr/RSPLIT;

    #pragma unroll
    for (int u = 0; u < 4; u++) {
        int row = u*32 + rowb;
        q4[u] = *(const float4*)(g_proj + ((size_t)(rbeg*Nn + i0+row))*PW + h*64 + c8);
        k4[u] = *(const float4*)(g_proj + ((size_t)(rbeg*Nn + j0+row))*PW + 512 + h*64 + c8);
        sc[u] = g_w[((i0+row)*Hh + h)*Rr + rbeg];
    }

    for (int r = rbeg; r < rend; ++r) {
        #pragma unroll
        for (int u = 0; u < 4; u++) {
            int row = u*32 + rowb;
            float4 a = q4[u];
            __half2 sc2 = __float2half2_rn(sc[u]);
            __half2* ah = (__half2*)&a;
            ah[0] = __hmul2(ah[0], sc2); ah[1] = __hmul2(ah[1], sc2);
            ah[2] = __hmul2(ah[2], sc2); ah[3] = __hmul2(ah[3], sc2);
            *(float4*)&Qs[row*LDH + c8] = a;
            *(float4*)&Ks[row*LDH + c8] = k4[u];
        }
        __syncthreads();
        if (r + 1 < rend) {
            #pragma unroll
            for (int u = 0; u < 4; u++) {
                int row = u*32 + rowb;
                q4[u] = *(const float4*)(g_proj + ((size_t)((r+1)*Nn + i0+row))*PW + h*64 + c8);
                k4[u] = *(const float4*)(g_proj + ((size_t)((r+1)*Nn + j0+row))*PW + 512 + h*64 + c8);
                sc[u] = g_w[((i0+row)*Hh + h)*Rr + r+1];
            }
        }
        #pragma unroll
        for (int ks = 0; ks < 4; ks++) {
            uint32_t af[4][4], bf[4][2];
            #pragma unroll
            for (int mf = 0; mf < 4; mf++)
                ldsm_x4(af[mf], qsB + (uint32_t)(((wm + mf*16 + aRow)*LDH + ks*16 + aCol)*2));
            #pragma unroll
            for (int nf = 0; nf < 4; nf++)
                ldsm_x2(bf[nf], ksB + (uint32_t)(((wn + nf*8 + bRow)*LDH + ks*16 + bCol)*2));
            #pragma unroll
            for (int mf = 0; mf < 4; mf++)
                #pragma unroll
                for (int nf = 0; nf < 4; nf++)
                    mma_f16(acc[mf][nf], af[mf], bf[nf]);
        }
        __syncthreads();
    }
    float* plane = g_dots + ((size_t)(rc*Hh + h))*Nn*Nn;
    #pragma unroll
    for (int mf = 0; mf < 4; mf++) {
        int i = i0 + wm + mf*16 + g;
        #pragma unroll
        for (int nf = 0; nf < 4; nf++) {
            int j = j0 + wn + nf*8 + 2*tig;
            *(float2*)&plane[(size_t)i*Nn + j] =
                make_float2(acc[mf][nf][0]*0.125f, acc[mf][nf][1]*0.125f);
            *(float2*)&plane[(size_t)(i+8)*Nn + j] =
                make_float2(acc[mf][nf][2]*0.125f, acc[mf][nf][3]*0.125f);
        }
    }
}

// ---------------- attention softmax over j (RSPLIT planes + transposed bias) -----
__global__ void __launch_bounds__(256)
softmax_kernel()
{
    const int row = blockIdx.x;            // h*256 + i
    const int h = row >> 8, j = threadIdx.x;
    float v = g_bias[(size_t)row*Nn + j];  // [h][i][j] — coalesced
    #pragma unroll
    for (int p = 0; p < RSPLIT; p++)
        v += g_dots[(((size_t)(p*Hh + h))*Nn + (row & 255))*Nn + j];
    __shared__ float red[8];
    const int lane = j & 31, wid = j >> 5;
    float m = v;
    #pragma unroll
    for (int o = 16; o; o >>= 1) m = fmaxf(m, __shfl_xor_sync(0xffffffffu, m, o));
    if (lane == 0) red[wid] = m;
    __syncthreads();
    float bm = red[0];
    #pragma unroll
    for (int k = 1; k < 8; k++) bm = fmaxf(bm, red[k]);
    __syncthreads();
    float e = __expf(v - bm);
    float s = e;
    #pragma unroll
    for (int o = 16; o; o >>= 1) s += __shfl_xor_sync(0xffffffffu, s, o);
    if (lane == 0) red[wid] = s;
    __syncthreads();
    float su = red[0];
    #pragma unroll
    for (int k = 1; k < 8; k++) su += red[k];
    g_attn[(size_t)row*Nn + j] = __float2half(e/su);
}

// ---------------- attn@V v3: cp.async double-buffered, dynamic smem --------------
// one block per (h,r), all 256 i-rows; V read once; low regs -> 2 blocks/SM
__global__ void __launch_bounds__(256)
attnv_f16_kernel()
{
    extern __shared__ __align__(16) __half dyn[];
    __half* As = dyn;                       // [2][256*LDH]
    __half* Vs = dyn + 2*256*LDH;           // [2][64*LDH]
    const int t = threadIdx.x;
    const int h = blockIdx.x, r = blockIdx.y;
    const int wid = t >> 5, lane = t & 31;
    const int wm = (wid & 3)*64, wn = (wid >> 2)*32;
    const int g = lane >> 2, tig = lane & 3;
    const int rowb = t >> 3, c8 = (t & 7)*8;
    const int aRow = ((lane>>3)&1)*8 + (lane&7);
    const int aCol = ((lane>>4)&1)*8;
    const int tRow = (lane & 7) + ((lane>>3)&1)*8;
    const uint32_t asB = (uint32_t)__cvta_generic_to_shared(As);
    const uint32_t vsB = (uint32_t)__cvta_generic_to_shared(Vs);
    float acc[4][4][4] = {};

    // prologue: stage 0 (k0 = 0)
    #pragma unroll
    for (int u = 0; u < 8; u++)
        cp16(&As[(u*32+rowb)*LDH + c8],
             g_attn + ((size_t)(h*Nn + u*32+rowb))*Nn + c8);
    #pragma unroll
    for (int u = 0; u < 2; u++)
        cp16(&Vs[(u*32+rowb)*LDH + c8],
             g_proj + ((size_t)(r*Nn + u*32+rowb))*PW + 1024 + h*64 + c8);
    CP_COMMIT();

    for (int kt = 0; kt < 4; kt++) {
        if (kt + 1 < 4) {
            int k0 = (kt+1)*64, s = (kt+1) & 1;
            #pragma unroll
            for (int u = 0; u < 8; u++)
                cp16(&As[(size_t)s*256*LDH + (u*32+rowb)*LDH + c8],
                     g_attn + ((size_t)(h*Nn + u*32+rowb))*Nn + k0 + c8);
            #pragma unroll
            for (int u = 0; u < 2; u++)
                cp16(&Vs[(size_t)s*64*LDH + (u*32+rowb)*LDH + c8],
                     g_proj + ((size_t)(r*Nn + k0 + u*32+rowb))*PW + 1024 + h*64 + c8);
        }
        CP_COMMIT();
        CP_WAIT1();
        __syncthreads();
        const uint32_t aBuf = asB + (uint32_t)((kt & 1)*256*LDH*2);
        const uint32_t vBuf = vsB + (uint32_t)((kt & 1)*64*LDH*2);
        #pragma unroll
        for (int ks = 0; ks < 4; ks++) {
            uint32_t af[4][4], bf[4][2];
            #pragma unroll
            for (int mf = 0; mf < 4; mf++)
                ldsm_x4(af[mf], aBuf + (uint32_t)(((wm + mf*16 + aRow)*LDH + ks*16 + aCol)*2));
            #pragma unroll
            for (int nf = 0; nf < 4; nf++)
                ldsm_x2_trans(bf[nf], vBuf + (uint32_t)(((ks*16 + tRow)*LDH + wn + nf*8)*2));
            #pragma unroll
            for (int mf = 0; mf < 4; mf++)
                #pragma unroll
                for (int nf = 0; nf < 4; nf++)
                    mma_f16(acc[mf][nf], af[mf], bf[nf]);
        }
        __syncthreads();
    }
    #pragma unroll
    for (int mf = 0; mf < 4; mf++) {
        int i = wm + mf*16 + g;
        #pragma unroll
        for (int nf = 0; nf < 4; nf++) {
            int c = h*64 + wn + nf*8 + 2*tig;
            *(__half2*)&g_ypre[((size_t)(r*Nn) + i)*INNERi + c] =
                __floats2half2_rn(acc[mf][nf][0], acc[mf][nf][1]);
            *(__half2*)&g_ypre[((size_t)(r*Nn) + i + 8)*INNERi + c] =
                __floats2half2_rn(acc[mf][nf][2], acc[mf][nf][3]);
        }
    }
}

// =================================================================================
extern "C" void kernel_launch(void* const* d_in, const int* in_sizes, int n_in,
                              void* d_out, int out_size)
{
    const float* x    = (const float*)d_in[0];
    const float* pair = (const float*)d_in[1];
    const float* wq   = (const float*)d_in[2];
    const float* wkv  = (const float*)d_in[3];
    const float* wo   = (const float*)d_in[4];
    const float* bo   = (const float*)d_in[5];
    const float* png  = (const float*)d_in[6];
    const float* pnb  = (const float*)d_in[7];
    const float* wp   = (const float*)d_in[8];
    const float* swqw = (const float*)d_in[9];
    const float* swqb = (const float*)d_in[10];
    const float* swkw = (const float*)d_in[11];
    const float* swkb = (const float*)d_in[12];
    float* out = (float*)d_out;

    __half *projh, *swph, *xh, *WpT, *WswT, *woT, *ypre;
    float *swb;
    cudaGetSymbolAddress((void**)&projh, g_proj);
    cudaGetSymbolAddress((void**)&swph,  g_swp);
    cudaGetSymbolAddress((void**)&xh,    g_xh);
    cudaGetSymbolAddress((void**)&WpT,   g_WpT);
    cudaGetSymbolAddress((void**)&WswT,  g_WswT);
    cudaGetSymbolAddress((void**)&woT,   g_woT);
    cudaGetSymbolAddress((void**)&ypre,  g_ypre);
    cudaGetSymbolAddress((void**)&swb,   g_swb);

    // side stream + events, created once on first (uncaptured) call
    static cudaStream_t s2 = nullptr;
    static cudaEvent_t evFork = nullptr, evPrep = nullptr, evSide = nullptr;
    if (s2 == nullptr) {
        cudaStreamCreateWithFlags(&s2, cudaStreamNonBlocking);
        cudaEventCreateWithFlags(&evFork, cudaEventDisableTiming);
        cudaEventCreateWithFlags(&evPrep, cudaEventDisableTiming);
        cudaEventCreateWithFlags(&evSide, cudaEventDisableTiming);
        cudaFuncSetAttribute(attnv_f16_kernel,
                             cudaFuncAttributeMaxDynamicSharedMemorySize, AVSMEM);
    }

    // fork: pairbias first on s2 (depends only on kernel inputs)
    cudaEventRecord(evFork, 0);
    cudaStreamWaitEvent(s2, evFork, 0);
    pairbias_kernel<<<Nn*Nn/128, 256, 0, s2>>>(pair, png, pnb, wp);

    // main: prep (x->half + weight packs)
    prep_kernel<<<(MROWS*Dd/4 + 255)/256, 256>>>(x, wq, wkv, swkw, swkb, swqw, swqb, wo);
    cudaEventRecord(evPrep, 0);

    // s2 (after prep): sw-gemm + seqw (hidden under proj)
    cudaStreamWaitEvent(s2, evPrep, 0);
    hgemm_kernel<true, 128><<<dim3(SWW/128, MROWS/128), 256, 0, s2>>>(
        xh, Dd, WswT, Dd, swb, swph, SWW, Dd);
    seqw_kernel<<<Nn, 128, 0, s2>>>();
    cudaEventRecord(evSide, s2);

    // main: full proj q|k|v
    hgemm_kernel<true, -1><<<dim3(PW/128, MROWS/128), 256>>>(
        xh, Dd, WpT, Dd, nullptr, projh, PW, Dd);

    // join: dots needs g_w (transitively pairbias ordered before evSide on s2)
    cudaStreamWaitEvent(0, evSide, 0);
    dots_f16_kernel<<<dim3(Nn/128, Nn/128, RSPLIT*Hh), 256>>>();
    softmax_kernel<<<Hh*Nn, 256>>>();
    attnv_f16_kernel<<<dim3(Hh, Rr), 256, AVSMEM>>>();
    hgemm_kernel<false, -1><<<dim3(Dd/128, MROWS/128), 256>>>(
        ypre, INNERi, woT, INNERi, bo, out, Dd, INNERi);
}